// round 15
// baseline (speedup 1.0000x reference)
#include <cuda_runtime.h>
#include <math.h>
#include <stdint.h>

#define TT 4096
#define DD 2048
#define FFDIM 8192
#define EE 8
#define MTILES 16   // covers up to 2048 tokens/expert (mean 512)

// ---------------- device scratch (static, no allocations) ----------------
__device__ uint16_t g_xh[(size_t)TT * DD];      // x as fp16 [T][D]
__device__ uint16_t g_Hh[(size_t)TT * FFDIM];   // H as fp16, sorted rows
__device__ int   g_idx[TT];
__device__ float g_w[TT];
__device__ int   g_counts[EE];
__device__ int   g_offsets[EE];
__device__ int   g_rank[TT];
__device__ int   g_perm[TT];

// ---------------- helpers ----------------
__device__ __forceinline__ uint32_t smem_u32(const void* p) {
    uint32_t a;
    asm("{ .reg .u64 t; cvta.to.shared.u64 t, %1; cvt.u32.u64 %0, t; }" : "=r"(a) : "l"(p));
    return a;
}
__device__ __forceinline__ uint32_t sw128(uint32_t b) { return b ^ ((b >> 3) & 0x70); }

__device__ __forceinline__ uint32_t cvt2h(float f0, float f1) {
    uint32_t h;
    asm("cvt.rn.f16x2.f32 %0, %1, %2;" : "=r"(h) : "f"(f1), "f"(f0));
    return h;
}

__device__ __forceinline__ void ldm4(uint32_t* r, uint32_t addr) {
    asm volatile("ldmatrix.sync.aligned.m8n8.x4.shared.b16 {%0,%1,%2,%3}, [%4];"
        : "=r"(r[0]), "=r"(r[1]), "=r"(r[2]), "=r"(r[3]) : "r"(addr));
}
__device__ __forceinline__ void ldm4t(uint32_t* r, uint32_t addr) {
    asm volatile("ldmatrix.sync.aligned.m8n8.x4.trans.shared.b16 {%0,%1,%2,%3}, [%4];"
        : "=r"(r[0]), "=r"(r[1]), "=r"(r[2]), "=r"(r[3]) : "r"(addr));
}
__device__ __forceinline__ void mma_f16(float* d, const uint32_t* a, uint32_t b0, uint32_t b1) {
    asm volatile("mma.sync.aligned.m16n8k16.row.col.f32.f16.f16.f32 "
        "{%0,%1,%2,%3}, {%4,%5,%6,%7}, {%8,%9}, {%0,%1,%2,%3};"
        : "+f"(d[0]), "+f"(d[1]), "+f"(d[2]), "+f"(d[3])
        : "r"(a[0]), "r"(a[1]), "r"(a[2]), "r"(a[3]), "r"(b0), "r"(b1));
}
#define CP16(dst, src) asm volatile("cp.async.cg.shared.global [%0], [%1], 16;" :: "r"(dst), "l"(src))
#define CP_COMMIT()    asm volatile("cp.async.commit_group;" ::: "memory")
#define CP_WAIT1()     asm volatile("cp.async.wait_group 1;" ::: "memory")
#define CP_WAIT0()     asm volatile("cp.async.wait_group 0;" ::: "memory")

__device__ __forceinline__ float gelu_exact(float v) {
    return 0.5f * v * (1.0f + erff(v * 0.70710678118654752440f));
}

// ---------------- pre-pass: x -> fp16 (32 MB, ~10us) ----------------
__global__ void cvt_x_kernel(const float* __restrict__ x) {
    size_t i4 = (size_t)blockIdx.x * 256 + threadIdx.x;
    float4 v = ((const float4*)x)[i4];
    ((uint2*)g_xh)[i4] = make_uint2(cvt2h(v.x, v.y), cvt2h(v.z, v.w));
}

// ---------------- router pipeline ----------------
__global__ void zero_counts_kernel() { if (threadIdx.x < EE) g_counts[threadIdx.x] = 0; }

__global__ void router_kernel(const float* __restrict__ x, const float* __restrict__ Wr) {
    const int t = blockIdx.x;
    const int warp = threadIdx.x >> 5, lane = threadIdx.x & 31;
    const float* xr = x + (size_t)t * DD;
    const float* wr = Wr + (size_t)warp * DD;
    float acc = 0.0f;
    for (int d = lane * 4; d < DD; d += 128) {
        float4 xv = *(const float4*)(xr + d);
        float4 wv = *(const float4*)(wr + d);
        acc += xv.x * wv.x + xv.y * wv.y + xv.z * wv.z + xv.w * wv.w;
    }
    #pragma unroll
    for (int o = 16; o; o >>= 1) acc += __shfl_xor_sync(0xFFFFFFFFu, acc, o);
    __shared__ float slog[EE];
    if (lane == 0) slog[warp] = acc;
    __syncthreads();
    if (threadIdx.x == 0) {
        float mx = slog[0]; int mi = 0;
        #pragma unroll
        for (int e = 1; e < EE; e++) if (slog[e] > mx) { mx = slog[e]; mi = e; }
        float s = 0.0f;
        #pragma unroll
        for (int e = 0; e < EE; e++) s += expf(slog[e] - mx);
        g_idx[t] = mi;
        g_w[t] = 1.0f / s;
        g_rank[t] = atomicAdd(&g_counts[mi], 1);
    }
}

__global__ void scan_kernel() {
    int s = 0;
    #pragma unroll
    for (int e = 0; e < EE; e++) { g_offsets[e] = s; s += g_counts[e]; }
}

__global__ void scatter_kernel() {
    int t = blockIdx.x * blockDim.x + threadIdx.x;
    if (t < TT) g_perm[g_offsets[g_idx[t]] + g_rank[t]] = t;
}

// ---------------- fp16 grouped GEMM: A cp.async ring, B fp32->fp16 in-kernel ----------------
// B smem layout: [k=64 rows][n=64 fp16] (natural W layout), consumed via ldmatrix.trans
// MODE 0: Hh = fp16( gelu( xh @ W1 ) )      K=DD,   N=FFDIM, W1=[E][K][N] fp32
// MODE 1: out = ( Hh @ W2 ) * w             K=FFDIM, N=DD,   W2=[E][K][N] fp32
constexpr int BM = 128, BN = 64, BKS = 64;
constexpr int A_TILE = BM * 128;                 // 16 KB (row = 64 fp16 = 128B)
constexpr int B_TILE = BKS * 128;                // 8 KB (row = 64 fp16 = 128B)
constexpr int SMEMT  = 3 * A_TILE + 2 * B_TILE;  // 64 KB

template<int MODE>
__global__ __launch_bounds__(128, 3) void moe_gemm_mma(
    const float* __restrict__ Bg, float* __restrict__ Cg)
{
    constexpr int K  = (MODE == 0) ? DD : FFDIM;
    constexpr int NN = (MODE == 0) ? FFDIM : DD;
    constexpr int KT = K / BKS;

    const int e   = blockIdx.z;
    const int cnt = g_counts[e];
    const int m0  = blockIdx.x * BM;             // m fastest -> B tile L2 reuse
    if (m0 >= cnt) return;
    const int off = g_offsets[e];
    const int n0  = blockIdx.y * BN;

    extern __shared__ __align__(1024) char smem[];
    const uint32_t su = smem_u32(smem);
    const int tid = threadIdx.x, wid = tid >> 5, lane = tid & 31;

    const char* Abase = (MODE == 0) ? (const char*)g_xh : (const char*)g_Hh;

    // ---- A cp.async geometry: kc = tid&7 (16B chunk of 128B row) ----
    const int kc = tid & 7;
    uint32_t aByte[8], sA[8];
    #pragma unroll
    for (int i = 0; i < 8; i++) {
        int m = (tid >> 3) + 16 * i;
        int r = m0 + m;
        bool v = r < cnt;
        uint32_t row;
        if (MODE == 0) row = (uint32_t)(v ? g_perm[off + r] : g_perm[off]);
        else           row = (uint32_t)(off + (v ? r : 0));
        aByte[i] = row * (uint32_t)(K * 2) + kc * 16u;
        sA[i] = sw128((uint32_t)(m * 128 + kc * 16));
    }

    // ---- B staging: thread owns half-row (32 fp32 = 8 float4), row rb = tid>>1 ----
    const int rb = tid >> 1, nh = tid & 1;       // k-row in tile, n-half (32 floats)
    const float* bPtr = Bg + (size_t)e * ((size_t)K * NN)
                        + (size_t)rb * NN + n0 + nh * 32;
    uint32_t sBst[8];
    #pragma unroll
    for (int i = 0; i < 8; i++)
        sBst[i] = sw128((uint32_t)(rb * 128 + nh * 64 + i * 8));

    // ---- ldmatrix geometry ----
    uint32_t aB[2], bBT;
    #pragma unroll
    for (int c = 0; c < 2; c++) {
        int row = wid * 32 + c * 16 + (lane & 15);
        aB[c] = (uint32_t)(row * 128 + (lane >> 4) * 16);
    }
    bBT = (uint32_t)((lane & 15) * 128 + (lane >> 4) * 16);   // trans: row=k, +16B per n-octet pair

    float acc[2][8][4];
    #pragma unroll
    for (int c = 0; c < 2; c++)
        #pragma unroll
        for (int j = 0; j < 8; j++)
            #pragma unroll
            for (int q = 0; q < 4; q++) acc[c][j][q] = 0.0f;

    float4 pb[8];
    auto preloadB = [&](int kt) {
        const float* p = bPtr + (size_t)(kt * BKS) * NN;
        #pragma unroll
        for (int i = 0; i < 8; i++) pb[i] = *(const float4*)(p + i * 4);
    };
    auto storeB = [&](int b) {
        char* Bs = smem + 3 * A_TILE + b * B_TILE;
        #pragma unroll
        for (int i = 0; i < 8; i++)
            *(uint2*)(Bs + sBst[i]) = make_uint2(cvt2h(pb[i].x, pb[i].y), cvt2h(pb[i].z, pb[i].w));
    };
    auto stageA = [&](int kt, int b) {
        const uint32_t d = su + b * A_TILE;
        const uint32_t ko = (uint32_t)(kt * 128);
        #pragma unroll
        for (int i = 0; i < 8; i++) CP16(d + sA[i], Abase + aByte[i] + ko);
    };

    stageA(0, 0); CP_COMMIT();
    stageA(1, 1); CP_COMMIT();
    preloadB(0); storeB(0);

    for (int kt = 0; kt < KT; kt++) {
        const bool more = (kt + 1 < KT);
        if (more) preloadB(kt + 1);              // B LDGs overlap MMA
        if (kt + 2 < KT) CP_WAIT1(); else CP_WAIT0();
        __syncthreads();                          // A[kt] + B[kt] visible
        if (kt + 2 < KT) { stageA(kt + 2, (kt + 2) % 3); CP_COMMIT(); }

        const uint32_t baseA = su + (kt % 3) * A_TILE;
        const uint32_t baseB = su + 3 * A_TILE + (kt & 1) * B_TILE;
        #pragma unroll
        for (int ks = 0; ks < 4; ks++) {
            uint32_t ah[2][4], bh[4][4];
            #pragma unroll
            for (int c = 0; c < 2; c++)
                ldm4(ah[c], baseA + sw128(aB[c] + ks * 32));
            #pragma unroll
            for (int j = 0; j < 4; j++)          // trans load: rows k, +32B per j (16 n)
                ldm4t(bh[j], baseB + sw128(bBT + ks * 2048 + j * 32));
            #pragma unroll
            for (int j = 0; j < 4; j++)
                #pragma unroll
                for (int c = 0; c < 2; c++) {
                    // trans pairing: n-octet0 = {r0,r1}, n-octet1 = {r2,r3}
                    mma_f16(acc[c][2 * j],     ah[c], bh[j][0], bh[j][1]);
                    mma_f16(acc[c][2 * j + 1], ah[c], bh[j][2], bh[j][3]);
                }
        }
        if (more) storeB((kt + 1) & 1);          // write other buffer; visible after next sync
    }

    // ---------------- epilogue ----------------
    const int mw = m0 + wid * 32;
    #pragma unroll
    for (int c = 0; c < 2; c++) {
        #pragma unroll
        for (int half = 0; half < 2; half++) {
            const int r = mw + c * 16 + (lane >> 2) + half * 8;
            if (r >= cnt) continue;
            if (MODE == 0) {
                uint16_t* hp = g_Hh + (size_t)(off + r) * FFDIM + n0;
                #pragma unroll
                for (int j = 0; j < 8; j++) {
                    float v0 = gelu_exact(acc[c][j][half * 2]);
                    float v1 = gelu_exact(acc[c][j][half * 2 + 1]);
                    *(uint32_t*)(hp + j * 8 + (lane & 3) * 2) = cvt2h(v0, v1);
                }
            } else {
                const int tok = g_perm[off + r];
                const float s = g_w[tok];
                float* cp = Cg + (size_t)tok * DD + n0;
                #pragma unroll
                for (int j = 0; j < 8; j++) {
                    float v0 = acc[c][j][half * 2] * s;
                    float v1 = acc[c][j][half * 2 + 1] * s;
                    *(float2*)(cp + j * 8 + (lane & 3) * 2) = make_float2(v0, v1);
                }
            }
        }
    }
}

// ---------------- launch ----------------
extern "C" void kernel_launch(void* const* d_in, const int* in_sizes, int n_in,
                              void* d_out, int out_size) {
    const float* x  = (const float*)d_in[0];
    const float* Wr = (const float*)d_in[1];
    const float* W1 = (const float*)d_in[2];
    const float* W2 = (const float*)d_in[3];
    float* out = (float*)d_out;

    cudaFuncSetAttribute(moe_gemm_mma<0>, cudaFuncAttributeMaxDynamicSharedMemorySize, SMEMT);
    cudaFuncSetAttribute(moe_gemm_mma<1>, cudaFuncAttributeMaxDynamicSharedMemorySize, SMEMT);

    cvt_x_kernel<<<TT * DD / 1024, 256>>>(x);
    zero_counts_kernel<<<1, 32>>>();
    router_kernel<<<TT, 256>>>(x, Wr);
    scan_kernel<<<1, 1>>>();
    scatter_kernel<<<TT / 256, 256>>>();

    dim3 g1(MTILES, FFDIM / BN, EE);
    moe_gemm_mma<0><<<g1, 128, SMEMT>>>(W1, nullptr);

    dim3 g2(MTILES, DD / BN, EE);
    moe_gemm_mma<1><<<g2, 128, SMEMT>>>(W2, out);
}